// round 13
// baseline (speedup 1.0000x reference)
#include <cuda_runtime.h>
#include <cuda_bf16.h>

// Features2im fused: analytic GK^{-1} + 2x2 stride-1 fold + count normalization.
//
// Per input row r (zero-padded out of range):
//   S_j = (a_j + a_{j-1}) + 0.5*(b_{j-1} - b_j)
//   T_j = 0.5*(c_j + c_{j-1}) + 0.5*(d_j - d_{j-1})
//   u = S - T (-> output row r), v = S + T (-> output row r+1)
//   out(i,j) = (u(i,j) + v(i-1,j)) * rinv(i) * cinv(j)
//
// Launch: EXACTLY 888 = 6 x 148 blocks (uniform 6/SM, single wave). The
// flattened (plane,row) space (256*513 rows) splits into 888 chunks of
// 147-148 rows; a chunk crosses at most ONE plane boundary -> explicit
// <=2-segment structure. Interior rows (1 <= i, i+1 <= 511) run a FAST loop
// with no validity predicates and rinv folded to 0.5; plane-boundary rows
// (0, 511, 512) take the generic path.
//
// Thread t owns columns 4t..4t+3 (one LDG.128 per input per row), carries
// v(i-1) in registers, depth-1 software pipeline with peeled last iteration.
// j-1 neighbor via __shfl_up; lane 0's left scalars prefetched in load_row
// (3 threads/block, L1-hit).

#define W_IN 512
#define H_IN 512
#define W_OUT 513
#define H_OUT 513
#define PLANE_IN (H_IN * W_IN)
#define PLANE_OUT (H_OUT * W_OUT)
#define NBLK 888
#define TOTAL_ROWS (256 * H_OUT)   // 131328

struct RowRegs {
    float4 a, b, c, d;     // owned 4 columns of each input
    float la, lb, lc, ld;  // left-neighbor scalars (meaningful on lane 0 only)
};

__device__ __forceinline__ float4 ldvec(const float* __restrict__ p, int r, int c0, bool valid)
{
    if (valid) return *reinterpret_cast<const float4*>(p + r * W_IN + c0);
    return make_float4(0.f, 0.f, 0.f, 0.f);
}

// Generic row load (zero-padded out of range).
__device__ __forceinline__ RowRegs load_row(const float* __restrict__ pa,
                                            const float* __restrict__ pb,
                                            const float* __restrict__ pc,
                                            const float* __restrict__ pd,
                                            int r, int c0, int lane, bool valid)
{
    RowRegs o;
    o.a = ldvec(pa, r, c0, valid);
    o.b = ldvec(pb, r, c0, valid);
    o.c = ldvec(pc, r, c0, valid);
    o.d = ldvec(pd, r, c0, valid);
    o.la = o.lb = o.lc = o.ld = 0.0f;
    if (lane == 0 && c0 != 0 && valid) {
        int off = r * W_IN + c0 - 1;
        o.la = pa[off]; o.lb = pb[off]; o.lc = pc[off]; o.ld = pd[off];
    }
    return o;
}

// Fast row load: row guaranteed in range.
__device__ __forceinline__ RowRegs load_row_fast(const float* __restrict__ pa,
                                                 const float* __restrict__ pb,
                                                 const float* __restrict__ pc,
                                                 const float* __restrict__ pd,
                                                 int r, int c0, int lane)
{
    RowRegs o;
    const int base = r * W_IN + c0;
    o.a = *reinterpret_cast<const float4*>(pa + base);
    o.b = *reinterpret_cast<const float4*>(pb + base);
    o.c = *reinterpret_cast<const float4*>(pc + base);
    o.d = *reinterpret_cast<const float4*>(pd + base);
    o.la = o.lb = o.lc = o.ld = 0.0f;
    if (lane == 0 && c0 != 0) {
        o.la = pa[base - 1]; o.lb = pb[base - 1];
        o.lc = pc[base - 1]; o.ld = pd[base - 1];
    }
    return o;
}

__device__ __forceinline__ void compute_ST(const RowRegs& r, int lane,
                                           float4& S, float4& T, float& S4, float& T4)
{
    float al = __shfl_up_sync(0xffffffffu, r.a.w, 1);
    float bl = __shfl_up_sync(0xffffffffu, r.b.w, 1);
    float cl = __shfl_up_sync(0xffffffffu, r.c.w, 1);
    float dl = __shfl_up_sync(0xffffffffu, r.d.w, 1);
    if (lane == 0) { al = r.la; bl = r.lb; cl = r.lc; dl = r.ld; }

    S.x = (r.a.x + al)    + 0.5f * (bl    - r.b.x);
    S.y = (r.a.y + r.a.x) + 0.5f * (r.b.x - r.b.y);
    S.z = (r.a.z + r.a.y) + 0.5f * (r.b.y - r.b.z);
    S.w = (r.a.w + r.a.z) + 0.5f * (r.b.z - r.b.w);
    T.x = 0.5f * (r.c.x + cl)    + 0.5f * (r.d.x - dl);
    T.y = 0.5f * (r.c.y + r.c.x) + 0.5f * (r.d.y - r.d.x);
    T.z = 0.5f * (r.c.z + r.c.y) + 0.5f * (r.d.z - r.d.y);
    T.w = 0.5f * (r.c.w + r.c.z) + 0.5f * (r.d.w - r.d.z);
    S4 = r.a.w + 0.5f * r.b.w;           // column 512 (thread 127 only)
    T4 = 0.5f * r.c.w - 0.5f * r.d.w;
}

// Generic emit (boundary rows): rinv selected per-row.
__device__ __forceinline__ void emit_row(float* __restrict__ po, int i,
                                         const float4& S, const float4& T,
                                         float S4, float T4,
                                         float4& vprev, float& vprev4,
                                         float ci0, bool last_thread, int c0)
{
    const float rinv = (i >= 1 && i < H_IN) ? 0.5f : 1.0f;
    const float rh = rinv * 0.5f;

    float* pr = po + (size_t)i * W_OUT + c0;
    pr[0] = ((S.x - T.x) + vprev.x) * (rinv * ci0);
    pr[1] = ((S.y - T.y) + vprev.y) * rh;
    pr[2] = ((S.z - T.z) + vprev.z) * rh;
    pr[3] = ((S.w - T.w) + vprev.w) * rh;
    if (last_thread) {
        po[(size_t)i * W_OUT + 512] = ((S4 - T4) + vprev4) * rinv;
    }

    vprev.x = S.x + T.x; vprev.y = S.y + T.y;
    vprev.z = S.z + T.z; vprev.w = S.w + T.w;
    vprev4  = S4 + T4;
}

// Fast emit (interior rows): rinv = 0.5 folded.
__device__ __forceinline__ void emit_row_fast(float* __restrict__ po, int i,
                                              const float4& S, const float4& T,
                                              float S4, float T4,
                                              float4& vprev, float& vprev4,
                                              float ci0h, bool last_thread, int c0)
{
    float* pr = po + (size_t)i * W_OUT + c0;
    pr[0] = ((S.x - T.x) + vprev.x) * ci0h;
    pr[1] = ((S.y - T.y) + vprev.y) * 0.25f;
    pr[2] = ((S.z - T.z) + vprev.z) * 0.25f;
    pr[3] = ((S.w - T.w) + vprev.w) * 0.25f;
    if (last_thread) {
        po[(size_t)i * W_OUT + 512] = ((S4 - T4) + vprev4) * 0.5f;
    }

    vprev.x = S.x + T.x; vprev.y = S.y + T.y;
    vprev.z = S.z + T.z; vprev.w = S.w + T.w;
    vprev4  = S4 + T4;
}

// Process one row segment [i0, i0+nrows) of one plane.
__device__ __forceinline__ void process_segment(
    const float* __restrict__ A, const float* __restrict__ B,
    const float* __restrict__ C, const float* __restrict__ D,
    float* __restrict__ out,
    int plane, int i0, int nrows,
    int c0, int lane, float ci0, bool last_thread)
{
    const float* pa = A + (size_t)plane * PLANE_IN;
    const float* pb = B + (size_t)plane * PLANE_IN;
    const float* pc = C + (size_t)plane * PLANE_IN;
    const float* pd = D + (size_t)plane * PLANE_IN;
    float* po = out + (size_t)plane * PLANE_OUT;

    const int ilast = i0 + nrows - 1;
    const float ci0h = ci0 * 0.5f;

    // Fast range: rows i with i >= 1 (rinv = 0.5) AND lookahead i+1 <= 511
    // (load always valid). Outside that, generic path.
    const int fast_lo = max(i0, 1);
    const int fast_hi = min(ilast, H_IN - 1);   // loop below runs i < fast_hi

    // prologue: v(i0-1)
    float4 vprev; float vprev4;
    {
        RowRegs r = load_row(pa, pb, pc, pd, i0 - 1, c0, lane, i0 >= 1);
        float4 S, T; float S4, T4;
        compute_ST(r, lane, S, T, S4, T4);
        vprev.x = S.x + T.x; vprev.y = S.y + T.y;
        vprev.z = S.z + T.z; vprev.w = S.w + T.w;
        vprev4  = S4 + T4;
    }

    // depth-1 pipeline: row i0 in flight
    RowRegs cur = load_row(pa, pb, pc, pd, i0, c0, lane, i0 < H_IN);

    int i = i0;

    // generic head (at most row 0 of a plane)
    for (; i < fast_lo && i < ilast; ++i) {
        RowRegs nxt = load_row(pa, pb, pc, pd, i + 1, c0, lane, i + 1 < H_IN);
        float4 S, T; float S4, T4;
        compute_ST(cur, lane, S, T, S4, T4);
        emit_row(po, i, S, T, S4, T4, vprev, vprev4, ci0, last_thread, c0);
        cur = nxt;
    }

    // fast interior loop: no validity predicates, rinv = 0.5
#pragma unroll 4
    for (; i < fast_hi; ++i) {
        RowRegs nxt = load_row_fast(pa, pb, pc, pd, i + 1, c0, lane);
        float4 S, T; float S4, T4;
        compute_ST(cur, lane, S, T, S4, T4);
        emit_row_fast(po, i, S, T, S4, T4, vprev, vprev4, ci0h, last_thread, c0);
        cur = nxt;
    }

    // generic tail (rows 511.. of a plane, still with lookahead)
    for (; i < ilast; ++i) {
        RowRegs nxt = load_row(pa, pb, pc, pd, i + 1, c0, lane, i + 1 < H_IN);
        float4 S, T; float S4, T4;
        compute_ST(cur, lane, S, T, S4, T4);
        emit_row(po, i, S, T, S4, T4, vprev, vprev4, ci0, last_thread, c0);
        cur = nxt;
    }

    // peeled last iteration: no lookahead load
    {
        float4 S, T; float S4, T4;
        compute_ST(cur, lane, S, T, S4, T4);
        emit_row(po, ilast, S, T, S4, T4, vprev, vprev4, ci0, last_thread, c0);
    }
}

__global__ __launch_bounds__(128, 6) void features2im_kernel(
    const float* __restrict__ A,
    const float* __restrict__ B,
    const float* __restrict__ C,
    const float* __restrict__ D,
    float* __restrict__ out)
{
    const int tid   = threadIdx.x;
    const int lane  = tid & 31;
    const int c0    = tid << 2;
    const bool last_thread = (tid == 127);
    const float ci0 = (c0 == 0) ? 1.0f : 0.5f;

    const int bid  = blockIdx.x;
    const int g0   = (int)(((long long)bid       * TOTAL_ROWS) / NBLK);
    const int gend = (int)(((long long)(bid + 1) * TOTAL_ROWS) / NBLK);
    const int nall = gend - g0;            // 147 or 148

    const int plane0 = g0 / H_OUT;
    const int i0     = g0 - plane0 * H_OUT;

    // Segment 1: rows [i0, i0+n1) in plane0
    const int n1 = min(H_OUT - i0, nall);
    process_segment(A, B, C, D, out, plane0, i0, n1, c0, lane, ci0, last_thread);

    // Segment 2 (at most one plane crossing): rows [0, nall-n1) in plane0+1
    const int n2 = nall - n1;
    if (n2 > 0) {
        process_segment(A, B, C, D, out, plane0 + 1, 0, n2, c0, lane, ci0, last_thread);
    }
}

extern "C" void kernel_launch(void* const* d_in, const int* in_sizes, int n_in,
                              void* d_out, int out_size)
{
    const float* a = (const float*)d_in[0];
    const float* b = (const float*)d_in[1];
    const float* c = (const float*)d_in[2];
    const float* d = (const float*)d_in[3];
    float* out = (float*)d_out;

    dim3 block(128);
    dim3 grid(NBLK);   // 888 = 6 x 148: uniform residency, single wave
    features2im_kernel<<<grid, block>>>(a, b, c, d, out);
}

// round 14
// speedup vs baseline: 1.0658x; 1.0658x over previous
#include <cuda_runtime.h>
#include <cuda_bf16.h>

// Features2im fused: analytic GK^{-1} + 2x2 stride-1 fold + count normalization.
//
// Per input row r (zero-padded out of range):
//   S_j = (a_j + a_{j-1}) + 0.5*(b_{j-1} - b_j)
//   T_j = 0.5*(c_j + c_{j-1}) + 0.5*(d_j - d_{j-1})
//   u = S - T (-> output row r), v = S + T (-> output row r+1)
//   out(i,j) = (u(i,j) + v(i-1,j)) * rinv(i) * cinv(j)
//
// Launch: EXACTLY 888 = 6 x 148 blocks (uniform 6/SM, single wave). The
// flattened (plane,row) space (256*513 rows) splits into 888 chunks of
// 147-148 rows; a chunk crosses at most ONE plane boundary, handled as an
// explicit <=2-segment structure (no generic while-loop state -> lower regs).
//
// Thread t owns columns 4t..4t+3 (one LDG.128 per input per row), carries
// v(i-1) in registers, depth-1 software pipeline with peeled last iteration
// (no dead lookahead load). j-1 neighbor via __shfl_up; lane 0's left scalars
// prefetched in load_row (3 threads/block, L1-hit).
//
// This configuration is the empirical optimum over 13 tuning rounds: traffic
// is at the compulsory minimum (~1.343 GB) and achieved bandwidth (~6.66 TB/s,
// 84% DRAM) is at the measured device ceiling for this 4:1 read:write stream
// mix. Perturbations tried and rejected: higher/lower occupancy, deeper
// pipelining, cache-streaming hints, loop splitting/interior specialization.

#define W_IN 512
#define H_IN 512
#define W_OUT 513
#define H_OUT 513
#define PLANE_IN (H_IN * W_IN)
#define PLANE_OUT (H_OUT * W_OUT)
#define NBLK 888
#define TOTAL_ROWS (256 * H_OUT)   // 131328

struct RowRegs {
    float4 a, b, c, d;     // owned 4 columns of each input
    float la, lb, lc, ld;  // left-neighbor scalars (meaningful on lane 0 only)
};

__device__ __forceinline__ float4 ldvec(const float* __restrict__ p, int r, int c0, bool valid)
{
    if (valid) return *reinterpret_cast<const float4*>(p + r * W_IN + c0);
    return make_float4(0.f, 0.f, 0.f, 0.f);
}

__device__ __forceinline__ RowRegs load_row(const float* __restrict__ pa,
                                            const float* __restrict__ pb,
                                            const float* __restrict__ pc,
                                            const float* __restrict__ pd,
                                            int r, int c0, int lane, bool valid)
{
    RowRegs o;
    o.a = ldvec(pa, r, c0, valid);
    o.b = ldvec(pb, r, c0, valid);
    o.c = ldvec(pc, r, c0, valid);
    o.d = ldvec(pd, r, c0, valid);
    o.la = o.lb = o.lc = o.ld = 0.0f;
    if (lane == 0 && c0 != 0 && valid) {     // 3 threads/block; same 128B line as lane 1 -> L1 hit
        int off = r * W_IN + c0 - 1;
        o.la = pa[off]; o.lb = pb[off]; o.lc = pc[off]; o.ld = pd[off];
    }
    return o;
}

__device__ __forceinline__ void compute_ST(const RowRegs& r, int lane,
                                           float4& S, float4& T, float& S4, float& T4)
{
    float al = __shfl_up_sync(0xffffffffu, r.a.w, 1);
    float bl = __shfl_up_sync(0xffffffffu, r.b.w, 1);
    float cl = __shfl_up_sync(0xffffffffu, r.c.w, 1);
    float dl = __shfl_up_sync(0xffffffffu, r.d.w, 1);
    if (lane == 0) { al = r.la; bl = r.lb; cl = r.lc; dl = r.ld; }

    S.x = (r.a.x + al)    + 0.5f * (bl    - r.b.x);
    S.y = (r.a.y + r.a.x) + 0.5f * (r.b.x - r.b.y);
    S.z = (r.a.z + r.a.y) + 0.5f * (r.b.y - r.b.z);
    S.w = (r.a.w + r.a.z) + 0.5f * (r.b.z - r.b.w);
    T.x = 0.5f * (r.c.x + cl)    + 0.5f * (r.d.x - dl);
    T.y = 0.5f * (r.c.y + r.c.x) + 0.5f * (r.d.y - r.d.x);
    T.z = 0.5f * (r.c.z + r.c.y) + 0.5f * (r.d.z - r.d.y);
    T.w = 0.5f * (r.c.w + r.c.z) + 0.5f * (r.d.w - r.d.z);
    S4 = r.a.w + 0.5f * r.b.w;           // column 512 (thread 127 only)
    T4 = 0.5f * r.c.w - 0.5f * r.d.w;
}

__device__ __forceinline__ void emit_row(float* __restrict__ po, int i,
                                         const float4& S, const float4& T,
                                         float S4, float T4,
                                         float4& vprev, float& vprev4,
                                         float ci0, bool last_thread, int c0)
{
    const float rinv = (i >= 1 && i < H_IN) ? 0.5f : 1.0f;
    const float rh = rinv * 0.5f;

    float* pr = po + (size_t)i * W_OUT + c0;
    pr[0] = ((S.x - T.x) + vprev.x) * (rinv * ci0);
    pr[1] = ((S.y - T.y) + vprev.y) * rh;
    pr[2] = ((S.z - T.z) + vprev.z) * rh;
    pr[3] = ((S.w - T.w) + vprev.w) * rh;
    if (last_thread) {
        po[(size_t)i * W_OUT + 512] = ((S4 - T4) + vprev4) * rinv;
    }

    vprev.x = S.x + T.x; vprev.y = S.y + T.y;
    vprev.z = S.z + T.z; vprev.w = S.w + T.w;
    vprev4  = S4 + T4;
}

// Process one row segment [i0, i0+nrows) of one plane.
__device__ __forceinline__ void process_segment(
    const float* __restrict__ A, const float* __restrict__ B,
    const float* __restrict__ C, const float* __restrict__ D,
    float* __restrict__ out,
    int plane, int i0, int nrows,
    int c0, int lane, float ci0, bool last_thread)
{
    const float* pa = A + (size_t)plane * PLANE_IN;
    const float* pb = B + (size_t)plane * PLANE_IN;
    const float* pc = C + (size_t)plane * PLANE_IN;
    const float* pd = D + (size_t)plane * PLANE_IN;
    float* po = out + (size_t)plane * PLANE_OUT;

    const int ilast = i0 + nrows - 1;

    // prologue: v(i0-1)
    float4 vprev; float vprev4;
    {
        RowRegs r = load_row(pa, pb, pc, pd, i0 - 1, c0, lane, i0 >= 1);
        float4 S, T; float S4, T4;
        compute_ST(r, lane, S, T, S4, T4);
        vprev.x = S.x + T.x; vprev.y = S.y + T.y;
        vprev.z = S.z + T.z; vprev.w = S.w + T.w;
        vprev4  = S4 + T4;
    }

    // depth-1 pipeline: row i0 in flight
    RowRegs cur = load_row(pa, pb, pc, pd, i0, c0, lane, i0 < H_IN);

#pragma unroll 4
    for (int i = i0; i < ilast; ++i) {
        RowRegs nxt = load_row(pa, pb, pc, pd, i + 1, c0, lane, i + 1 < H_IN);

        float4 S, T; float S4, T4;
        compute_ST(cur, lane, S, T, S4, T4);
        emit_row(po, i, S, T, S4, T4, vprev, vprev4, ci0, last_thread, c0);

        cur = nxt;
    }

    // peeled last iteration: no lookahead load
    {
        float4 S, T; float S4, T4;
        compute_ST(cur, lane, S, T, S4, T4);
        emit_row(po, ilast, S, T, S4, T4, vprev, vprev4, ci0, last_thread, c0);
    }
}

__global__ __launch_bounds__(128, 6) void features2im_kernel(
    const float* __restrict__ A,
    const float* __restrict__ B,
    const float* __restrict__ C,
    const float* __restrict__ D,
    float* __restrict__ out)
{
    const int tid   = threadIdx.x;
    const int lane  = tid & 31;
    const int c0    = tid << 2;
    const bool last_thread = (tid == 127);
    const float ci0 = (c0 == 0) ? 1.0f : 0.5f;

    const int bid  = blockIdx.x;
    const int g0   = (int)(((long long)bid       * TOTAL_ROWS) / NBLK);
    const int gend = (int)(((long long)(bid + 1) * TOTAL_ROWS) / NBLK);
    const int nall = gend - g0;            // 147 or 148

    const int plane0 = g0 / H_OUT;
    const int i0     = g0 - plane0 * H_OUT;

    // Segment 1: rows [i0, i0+n1) in plane0
    const int n1 = min(H_OUT - i0, nall);
    process_segment(A, B, C, D, out, plane0, i0, n1, c0, lane, ci0, last_thread);

    // Segment 2 (at most one plane crossing): rows [0, nall-n1) in plane0+1
    const int n2 = nall - n1;
    if (n2 > 0) {
        process_segment(A, B, C, D, out, plane0 + 1, 0, n2, c0, lane, ci0, last_thread);
    }
}

extern "C" void kernel_launch(void* const* d_in, const int* in_sizes, int n_in,
                              void* d_out, int out_size)
{
    const float* a = (const float*)d_in[0];
    const float* b = (const float*)d_in[1];
    const float* c = (const float*)d_in[2];
    const float* d = (const float*)d_in[3];
    float* out = (float*)d_out;

    dim3 block(128);
    dim3 grid(NBLK);   // 888 = 6 x 148: uniform residency, single wave
    features2im_kernel<<<grid, block>>>(a, b, c, d, out);
}